// round 1
// baseline (speedup 1.0000x reference)
#include <cuda_runtime.h>
#include <cstddef>

#define BATCH   8
#define T_LEN   4096
#define HC      256
#define HD      512          // 2*HC
#define NROWS   (BATCH * T_LEN)   // 32768

// Scratch (device globals: allocation-free per harness rules)
__device__ float g_wx[BATCH * T_LEN * HD];   // 64 MB: input-projection output
__device__ float g_h0[BATCH * T_LEN * HD];   // 64 MB: layer-0 hidden states

// ---------------------------------------------------------------------------
// Projection GEMM:  Y[N,512] = X[N,512] @ Mw[512,512] + bias
// Mw[k][j]:  k<256: (j<256 ? wr[k][j] : wi[k][j-256])
//            k>=256:(j<256 ? -wi[k-256][j] : wr[k-256][j-256])
// bias[j] = j<256 ? br[j] : bi[j-256]
// BM=128, BN=128, BK=16, 256 threads, 8x8 register tile.
// ---------------------------------------------------------------------------
__global__ __launch_bounds__(256) void proj_kernel(
    const float* __restrict__ X,
    const float* __restrict__ wr, const float* __restrict__ wi,
    const float* __restrict__ br, const float* __restrict__ bi,
    float* __restrict__ Y)
{
    __shared__ float As[16][132];   // [k][m], pad keeps float4 16B-aligned (132*4=528, 528%16==0)
    __shared__ float Bs[16][132];   // [k][j]

    const int bm  = blockIdx.x * 128;
    const int bn  = blockIdx.y * 128;
    const int tid = threadIdx.x;
    const int tx  = tid & 15;       // 0..15 -> 8 output cols
    const int ty  = tid >> 4;       // 0..15 -> 8 output rows

    // A-load mapping: each thread loads 8 consecutive k of one row
    const int am = tid >> 1;              // 0..127
    const int ak = (tid & 1) * 8;         // 0 or 8
    // B-load mapping: each thread loads 8 consecutive j of one k-row
    const int bk = tid >> 4;              // 0..15
    const int bj = (tid & 15) * 8;        // 0..120
    const bool jhi = (bn + bj) >= 256;
    const int  jj  = (bn + bj) & 255;

    float acc[8][8];
#pragma unroll
    for (int r = 0; r < 8; ++r)
#pragma unroll
        for (int c = 0; c < 8; ++c) acc[r][c] = 0.f;

    for (int k0 = 0; k0 < HD; k0 += 16) {
        // ---- load A tile (transposed into As[k][m]) ----
        const float* xrow = X + (size_t)(bm + am) * HD + k0 + ak;
        float4 a0 = *(const float4*)(xrow);
        float4 a1 = *(const float4*)(xrow + 4);
        As[ak + 0][am] = a0.x; As[ak + 1][am] = a0.y;
        As[ak + 2][am] = a0.z; As[ak + 3][am] = a0.w;
        As[ak + 4][am] = a1.x; As[ak + 5][am] = a1.y;
        As[ak + 6][am] = a1.z; As[ak + 7][am] = a1.w;

        // ---- load B tile (Mw rows k0+bk, cols bn+bj..+7) ----
        {
            int k = k0 + bk;
            float4 b0, b1;
            if (k < 256) {
                const float* src = (jhi ? wi : wr) + (size_t)k * 256 + jj;
                b0 = *(const float4*)(src);
                b1 = *(const float4*)(src + 4);
            } else {
                const float* src = (jhi ? wr : wi) + (size_t)(k - 256) * 256 + jj;
                b0 = *(const float4*)(src);
                b1 = *(const float4*)(src + 4);
                if (!jhi) {
                    b0.x = -b0.x; b0.y = -b0.y; b0.z = -b0.z; b0.w = -b0.w;
                    b1.x = -b1.x; b1.y = -b1.y; b1.z = -b1.z; b1.w = -b1.w;
                }
            }
            *(float4*)&Bs[bk][bj]     = b0;
            *(float4*)&Bs[bk][bj + 4] = b1;
        }
        __syncthreads();

#pragma unroll
        for (int kk = 0; kk < 16; ++kk) {
            float4 av0 = *(const float4*)&As[kk][ty * 8];
            float4 av1 = *(const float4*)&As[kk][ty * 8 + 4];
            float4 bv0 = *(const float4*)&Bs[kk][tx * 8];
            float4 bv1 = *(const float4*)&Bs[kk][tx * 8 + 4];
            float a[8] = {av0.x, av0.y, av0.z, av0.w, av1.x, av1.y, av1.z, av1.w};
            float b[8] = {bv0.x, bv0.y, bv0.z, bv0.w, bv1.x, bv1.y, bv1.z, bv1.w};
#pragma unroll
            for (int r = 0; r < 8; ++r)
#pragma unroll
                for (int c = 0; c < 8; ++c)
                    acc[r][c] = fmaf(a[r], b[c], acc[r][c]);
        }
        __syncthreads();
    }

    // ---- epilogue: add bias, store ----
    const int col0 = bn + tx * 8;
    float bias[8];
#pragma unroll
    for (int c = 0; c < 8; ++c) {
        int j = col0 + c;
        bias[c] = (j < 256) ? br[j] : bi[j - 256];
    }
#pragma unroll
    for (int r = 0; r < 8; ++r) {
        float* yrow = Y + (size_t)(bm + ty * 8 + r) * HD + col0;
        float4 v0 = make_float4(acc[r][0] + bias[0], acc[r][1] + bias[1],
                                acc[r][2] + bias[2], acc[r][3] + bias[3]);
        float4 v1 = make_float4(acc[r][4] + bias[4], acc[r][5] + bias[5],
                                acc[r][6] + bias[6], acc[r][7] + bias[7]);
        *(float4*)(yrow)     = v0;
        *(float4*)(yrow + 4) = v1;
    }
}

// ---------------------------------------------------------------------------
// Recurrent scan.
// Grid: 64 CTAs = 8 clusters (one per batch) x 8 CTAs (64 output reals each).
// Each thread (kg,jg) holds M[k0..k0+31][j0..j0+3] in registers.
// M[k][j]: k<256: (j<256 ? ur[k][j] : ui[k][j-256])
//          k>=256:(j<256 ? -ui[k-256][j] : ur[k-256][j-256])
// h exchange through `out` rows + cluster barrier (release/acquire).
// ---------------------------------------------------------------------------
__global__ void __cluster_dims__(8, 1, 1) __launch_bounds__(256, 1)
scan_kernel(const float* __restrict__ wx,
            const float* __restrict__ ur, const float* __restrict__ ui,
            const float* __restrict__ ubr, const float* __restrict__ ubi,
            float* out)
{
    unsigned rank;
    asm("mov.u32 %0, %%cluster_ctarank;" : "=r"(rank));
    const int b   = blockIdx.x >> 3;
    const int tid = threadIdx.x;
    const int jg  = tid >> 4;        // 0..15 -> 4 outputs each
    const int kg  = tid & 15;        // 0..15 -> 32 k's each
    const int j0  = (int)rank * 64 + jg * 4;
    const int k0  = kg * 32;
    const bool jhi = (j0 >= 256);
    const int  jj  = j0 & 255;

    // ---- load weight slice into registers ----
    float w[4][32];
    {
        const float* srcA = jhi ? ui : ur;   // rows k<256
        const float* srcB = jhi ? ur : ui;   // rows k>=256
        const float  sgnB = jhi ? 1.f : -1.f;
#pragma unroll
        for (int i = 0; i < 32; ++i) {
            int k = k0 + i;
            float4 v;
            if (k < 256) {
                v = *(const float4*)(srcA + (size_t)k * 256 + jj);
            } else {
                v = *(const float4*)(srcB + (size_t)(k - 256) * 256 + jj);
                v.x *= sgnB; v.y *= sgnB; v.z *= sgnB; v.w *= sgnB;
            }
            w[0][i] = v.x; w[1][i] = v.y; w[2][i] = v.z; w[3][i] = v.w;
        }
    }
    const float4 ub = jhi ? *(const float4*)(ubi + jj)
                          : *(const float4*)(ubr + jj);

    const float* wx_b  = wx  + (size_t)b * (T_LEN * HD);
    float*       out_b = out + (size_t)b * (T_LEN * HD);

    // ---- t = 0: h_prev = 0 ----
    if (kg == 0) {
        float4 wv = *(const float4*)(wx_b + j0);
        float4 y;
        y.x = tanhf(wv.x + ub.x);
        y.y = tanhf(wv.y + ub.y);
        y.z = tanhf(wv.z + ub.z);
        y.w = tanhf(wv.w + ub.w);
        *(float4*)(out_b + j0) = y;
    }
    asm volatile("barrier.cluster.arrive.aligned;" ::: "memory");

    for (int t = 1; t < T_LEN; ++t) {
        // prefetch this step's wx before waiting (independent of h)
        float4 wv;
        if (kg == 0) wv = *(const float4*)(wx_b + (size_t)t * HD + j0);

        asm volatile("barrier.cluster.wait.aligned;" ::: "memory");

        const float* hp = out_b + (size_t)(t - 1) * HD + k0;
        float hs[32];
#pragma unroll
        for (int q = 0; q < 8; ++q) {
            float4 v = *(const float4*)(hp + q * 4);
            hs[q * 4 + 0] = v.x; hs[q * 4 + 1] = v.y;
            hs[q * 4 + 2] = v.z; hs[q * 4 + 3] = v.w;
        }

        float a0 = 0.f, a1 = 0.f, a2 = 0.f, a3 = 0.f;
#pragma unroll
        for (int i = 0; i < 32; ++i) {
            a0 = fmaf(hs[i], w[0][i], a0);
            a1 = fmaf(hs[i], w[1][i], a1);
            a2 = fmaf(hs[i], w[2][i], a2);
            a3 = fmaf(hs[i], w[3][i], a3);
        }
        // reduce across 16 kg lanes (xor of lane bits 0..3 stays in-half)
#pragma unroll
        for (int off = 1; off < 16; off <<= 1) {
            a0 += __shfl_xor_sync(0xffffffffu, a0, off);
            a1 += __shfl_xor_sync(0xffffffffu, a1, off);
            a2 += __shfl_xor_sync(0xffffffffu, a2, off);
            a3 += __shfl_xor_sync(0xffffffffu, a3, off);
        }
        if (kg == 0) {
            float4 y;
            y.x = tanhf(wv.x + ub.x + a0);
            y.y = tanhf(wv.y + ub.y + a1);
            y.z = tanhf(wv.z + ub.z + a2);
            y.w = tanhf(wv.w + ub.w + a3);
            *(float4*)(out_b + (size_t)t * HD + j0) = y;
        }
        asm volatile("barrier.cluster.arrive.aligned;" ::: "memory");
    }
    // balance the final arrive
    asm volatile("barrier.cluster.wait.aligned;" ::: "memory");
}

// ---------------------------------------------------------------------------
extern "C" void kernel_launch(void* const* d_in, const int* in_sizes, int n_in,
                              void* d_out, int out_size)
{
    const float* x      = (const float*)d_in[0];
    const float* l0_wr  = (const float*)d_in[1];
    const float* l0_wi  = (const float*)d_in[2];
    const float* l0_wbr = (const float*)d_in[3];
    const float* l0_wbi = (const float*)d_in[4];
    const float* l0_ur  = (const float*)d_in[5];
    const float* l0_ui  = (const float*)d_in[6];
    const float* l0_ubr = (const float*)d_in[7];
    const float* l0_ubi = (const float*)d_in[8];
    const float* l1_wr  = (const float*)d_in[9];
    const float* l1_wi  = (const float*)d_in[10];
    const float* l1_wbr = (const float*)d_in[11];
    const float* l1_wbi = (const float*)d_in[12];
    const float* l1_ur  = (const float*)d_in[13];
    const float* l1_ui  = (const float*)d_in[14];
    const float* l1_ubr = (const float*)d_in[15];
    const float* l1_ubi = (const float*)d_in[16];

    float* out = (float*)d_out;

    void *p_wx_v = nullptr, *p_h0_v = nullptr;
    cudaGetSymbolAddress(&p_wx_v, g_wx);
    cudaGetSymbolAddress(&p_h0_v, g_h0);
    float* p_wx = (float*)p_wx_v;
    float* p_h0 = (float*)p_h0_v;

    dim3 pgrid(NROWS / 128, HD / 128);   // 256 x 4

    // layer 0
    proj_kernel<<<pgrid, 256>>>(x, l0_wr, l0_wi, l0_wbr, l0_wbi, p_wx);
    scan_kernel<<<64, 256>>>(p_wx, l0_ur, l0_ui, l0_ubr, l0_ubi, p_h0);
    // layer 1
    proj_kernel<<<pgrid, 256>>>(p_h0, l1_wr, l1_wi, l1_wbr, l1_wbi, p_wx);
    scan_kernel<<<64, 256>>>(p_wx, l1_ur, l1_ui, l1_ubr, l1_ubi, out);
}

// round 2
// speedup vs baseline: 1.4198x; 1.4198x over previous
#include <cuda_runtime.h>
#include <cstddef>

#define BATCH   8
#define T_LEN   4096
#define HC      256
#define HD      512
#define NROWS   (BATCH * T_LEN)

__device__ float g_wx[NROWS * HD];   // input-projection output
__device__ float g_h0[NROWS * HD];   // layer-0 hidden states

// ---------------------------------------------------------------- helpers
static __device__ __forceinline__ unsigned su32(const void* p) {
    return (unsigned)__cvta_generic_to_shared(p);
}
static __device__ __forceinline__ unsigned long long packf2(float lo, float hi) {
    unsigned long long r;
    asm("mov.b64 %0, {%1, %2};" : "=l"(r) : "f"(lo), "f"(hi));
    return r;
}
static __device__ __forceinline__ void unpackf2(unsigned long long v, float& lo, float& hi) {
    asm("mov.b64 {%0, %1}, %2;" : "=f"(lo), "=f"(hi) : "l"(v));
}
static __device__ __forceinline__ float fast_tanh(float x) {
    // 1 - 2/(e^{2x}+1); saturates correctly: e->inf => 1, e->0 => -1
    float e = __expf(2.0f * x);
    return 1.0f - __fdividef(2.0f, e + 1.0f);
}
static __device__ __forceinline__ void mbar_wait(unsigned addr, unsigned parity) {
    asm volatile(
        "{\n\t.reg .pred P;\n"
        "LW_%=:\n\t"
        "mbarrier.try_wait.parity.acquire.cluster.shared::cta.b64 P, [%0], %1, 0x989680;\n\t"
        "@P bra LD_%=;\n\t"
        "bra LW_%=;\n"
        "LD_%=:\n\t}"
        :: "r"(addr), "r"(parity) : "memory");
}

// ---------------------------------------------------------------------------
// Projection GEMM:  Y[N,512] = X[N,512] @ Mw[512,512] + bias  (unchanged)
// ---------------------------------------------------------------------------
__global__ __launch_bounds__(256) void proj_kernel(
    const float* __restrict__ X,
    const float* __restrict__ wr, const float* __restrict__ wi,
    const float* __restrict__ br, const float* __restrict__ bi,
    float* __restrict__ Y)
{
    __shared__ float As[16][132];
    __shared__ float Bs[16][132];

    const int bm  = blockIdx.x * 128;
    const int bn  = blockIdx.y * 128;
    const int tid = threadIdx.x;
    const int tx  = tid & 15;
    const int ty  = tid >> 4;

    const int am = tid >> 1;
    const int ak = (tid & 1) * 8;
    const int bk = tid >> 4;
    const int bj = (tid & 15) * 8;
    const bool jhi = (bn + bj) >= 256;
    const int  jj  = (bn + bj) & 255;

    float acc[8][8];
#pragma unroll
    for (int r = 0; r < 8; ++r)
#pragma unroll
        for (int c = 0; c < 8; ++c) acc[r][c] = 0.f;

    for (int k0 = 0; k0 < HD; k0 += 16) {
        const float* xrow = X + (size_t)(bm + am) * HD + k0 + ak;
        float4 a0 = *(const float4*)(xrow);
        float4 a1 = *(const float4*)(xrow + 4);
        As[ak + 0][am] = a0.x; As[ak + 1][am] = a0.y;
        As[ak + 2][am] = a0.z; As[ak + 3][am] = a0.w;
        As[ak + 4][am] = a1.x; As[ak + 5][am] = a1.y;
        As[ak + 6][am] = a1.z; As[ak + 7][am] = a1.w;
        {
            int k = k0 + bk;
            float4 b0, b1;
            if (k < 256) {
                const float* src = (jhi ? wi : wr) + (size_t)k * 256 + jj;
                b0 = *(const float4*)(src);
                b1 = *(const float4*)(src + 4);
            } else {
                const float* src = (jhi ? wr : wi) + (size_t)(k - 256) * 256 + jj;
                b0 = *(const float4*)(src);
                b1 = *(const float4*)(src + 4);
                if (!jhi) {
                    b0.x = -b0.x; b0.y = -b0.y; b0.z = -b0.z; b0.w = -b0.w;
                    b1.x = -b1.x; b1.y = -b1.y; b1.z = -b1.z; b1.w = -b1.w;
                }
            }
            *(float4*)&Bs[bk][bj]     = b0;
            *(float4*)&Bs[bk][bj + 4] = b1;
        }
        __syncthreads();

#pragma unroll
        for (int kk = 0; kk < 16; ++kk) {
            float4 av0 = *(const float4*)&As[kk][ty * 8];
            float4 av1 = *(const float4*)&As[kk][ty * 8 + 4];
            float4 bv0 = *(const float4*)&Bs[kk][tx * 8];
            float4 bv1 = *(const float4*)&Bs[kk][tx * 8 + 4];
            float a[8] = {av0.x, av0.y, av0.z, av0.w, av1.x, av1.y, av1.z, av1.w};
            float b[8] = {bv0.x, bv0.y, bv0.z, bv0.w, bv1.x, bv1.y, bv1.z, bv1.w};
#pragma unroll
            for (int r = 0; r < 8; ++r)
#pragma unroll
                for (int c = 0; c < 8; ++c)
                    acc[r][c] = fmaf(a[r], b[c], acc[r][c]);
        }
        __syncthreads();
    }

    const int col0 = bn + tx * 8;
    float bias[8];
#pragma unroll
    for (int c = 0; c < 8; ++c) {
        int j = col0 + c;
        bias[c] = (j < 256) ? br[j] : bi[j - 256];
    }
#pragma unroll
    for (int r = 0; r < 8; ++r) {
        float* yrow = Y + (size_t)(bm + ty * 8 + r) * HD + col0;
        float4 v0 = make_float4(acc[r][0] + bias[0], acc[r][1] + bias[1],
                                acc[r][2] + bias[2], acc[r][3] + bias[3]);
        float4 v1 = make_float4(acc[r][4] + bias[4], acc[r][5] + bias[5],
                                acc[r][6] + bias[6], acc[r][7] + bias[7]);
        *(float4*)(yrow)     = v0;
        *(float4*)(yrow + 4) = v1;
    }
}

// ---------------------------------------------------------------------------
// Recurrent scan: 8 clusters (one per batch) x 8 CTAs x 256 threads.
// h exchanged via DSMEM broadcast (st.shared::cluster) + mbarrier (count=128:
// 8 src CTAs x 8 warps x 2 producer lanes), double-buffered.
// Thread (jg=tid>>4, kg=tid&15): outputs j0=rank*64+jg*4..+3,
// k-slice interleaved k = q*64 + kg*4 .. +3, q=0..7 (2-way LDS conflicts only).
// Math uses packed fma.rn.f32x2 (2 MACs/instr).
// ---------------------------------------------------------------------------
__global__ void __cluster_dims__(8, 1, 1) __launch_bounds__(256, 1)
scan_kernel(const float* __restrict__ wx,
            const float* __restrict__ ur, const float* __restrict__ ui,
            const float* __restrict__ ubr, const float* __restrict__ ubi,
            float* __restrict__ out)
{
    __shared__ float hbuf[2][HD];
    __shared__ __align__(8) unsigned long long mbar[2];

    unsigned rank;
    asm("mov.u32 %0, %%cluster_ctarank;" : "=r"(rank));
    const int b    = blockIdx.x >> 3;
    const int tid  = threadIdx.x;
    const int lane = tid & 31;
    const int jg   = tid >> 4;
    const int kg   = tid & 15;
    const int j0   = (int)rank * 64 + jg * 4;
    const int jj   = j0 & 255;
    const bool jhi = j0 >= 256;

    const unsigned hb_u32 = su32(&hbuf[0][0]);
    const unsigned mb_u32 = su32(&mbar[0]);

    if (tid == 0) {
        asm volatile("mbarrier.init.shared.b64 [%0], %1;" :: "r"(mb_u32),     "r"(128u) : "memory");
        asm volatile("mbarrier.init.shared.b64 [%0], %1;" :: "r"(mb_u32 + 8), "r"(128u) : "memory");
    }
    __syncthreads();
    asm volatile("barrier.cluster.arrive.aligned;" ::: "memory");
    asm volatile("barrier.cluster.wait.aligned;"   ::: "memory");

    // ---- weight slice into registers, packed f32x2 along k ----
    unsigned long long w2[4][16];
#pragma unroll
    for (int q = 0; q < 8; ++q) {
        const int k = q * 64 + kg * 4;
        float4 r0, r1, r2, r3;
        if (k < 256) {
            const float* src = (jhi ? ui : ur) + (size_t)k * 256 + jj;
            r0 = *(const float4*)(src);
            r1 = *(const float4*)(src + 256);
            r2 = *(const float4*)(src + 512);
            r3 = *(const float4*)(src + 768);
        } else {
            const float* src = (jhi ? ur : ui) + (size_t)(k - 256) * 256 + jj;
            const float s = jhi ? 1.f : -1.f;
            r0 = *(const float4*)(src);
            r1 = *(const float4*)(src + 256);
            r2 = *(const float4*)(src + 512);
            r3 = *(const float4*)(src + 768);
            r0.x *= s; r0.y *= s; r0.z *= s; r0.w *= s;
            r1.x *= s; r1.y *= s; r1.z *= s; r1.w *= s;
            r2.x *= s; r2.y *= s; r2.z *= s; r2.w *= s;
            r3.x *= s; r3.y *= s; r3.z *= s; r3.w *= s;
        }
        w2[0][2*q]   = packf2(r0.x, r1.x);
        w2[1][2*q]   = packf2(r0.y, r1.y);
        w2[2][2*q]   = packf2(r0.z, r1.z);
        w2[3][2*q]   = packf2(r0.w, r1.w);
        w2[0][2*q+1] = packf2(r2.x, r3.x);
        w2[1][2*q+1] = packf2(r2.y, r3.y);
        w2[2][2*q+1] = packf2(r2.z, r3.z);
        w2[3][2*q+1] = packf2(r2.w, r3.w);
    }
    const float4 ub = jhi ? *(const float4*)(ubi + jj)
                          : *(const float4*)(ubr + jj);

    // producers: lanes 0-7 (jg even half) and 16-23 (jg odd half)
    const bool prod = ((lane >> 3) & 1) == 0;
    const int  dst  = lane & 7;
    unsigned dsth, dstm;
    asm("mapa.shared::cluster.u32 %0, %1, %2;" : "=r"(dsth) : "r"(hb_u32), "r"(dst));
    asm("mapa.shared::cluster.u32 %0, %1, %2;" : "=r"(dstm) : "r"(mb_u32), "r"(dst));
    const unsigned stoff = (unsigned)(rank * 256 + jg * 16);

    const float* wx_b  = wx  + (size_t)b * (T_LEN * HD);
    float*       out_b = out + (size_t)b * (T_LEN * HD);

    // ---- t = 0 (h_prev = 0) ----
    {
        float4 wv = *(const float4*)(wx_b + j0);
        float4 yv;
        yv.x = fast_tanh(wv.x + ub.x);
        yv.y = fast_tanh(wv.y + ub.y);
        yv.z = fast_tanh(wv.z + ub.z);
        yv.w = fast_tanh(wv.w + ub.w);
        if ((lane & 15) == 8) *(float4*)(out_b + j0) = yv;
        if (prod) {
            unsigned long long y01 = packf2(yv.x, yv.y);
            unsigned long long y23 = packf2(yv.z, yv.w);
            unsigned a = dsth + stoff;            // buf 0
            asm volatile("st.shared::cluster.b64 [%0], %1;" :: "r"(a),     "l"(y01) : "memory");
            asm volatile("st.shared::cluster.b64 [%0], %1;" :: "r"(a + 8), "l"(y23) : "memory");
            asm volatile("mbarrier.arrive.release.cluster.shared::cluster.b64 _, [%0];"
                         :: "r"(dstm) : "memory");
        }
    }

    for (int t = 1; t < T_LEN; ++t) {
        float4 wv = *(const float4*)(wx_b + (size_t)t * HD + j0);

        const int use = t - 1;
        const int rbuf = use & 1;
        mbar_wait(mb_u32 + rbuf * 8, (unsigned)((use >> 1) & 1));

        unsigned long long h2[16];
        const float* hp = &hbuf[rbuf][0];
#pragma unroll
        for (int q = 0; q < 8; ++q) {
            ulonglong2 v = *(const ulonglong2*)(hp + q * 64 + kg * 4);
            h2[2*q]   = v.x;
            h2[2*q+1] = v.y;
        }

        unsigned long long acc0 = 0, acc1 = 0, acc2 = 0, acc3 = 0;
#pragma unroll
        for (int q = 0; q < 16; ++q) {
            asm("fma.rn.f32x2 %0, %1, %2, %0;" : "+l"(acc0) : "l"(h2[q]), "l"(w2[0][q]));
            asm("fma.rn.f32x2 %0, %1, %2, %0;" : "+l"(acc1) : "l"(h2[q]), "l"(w2[1][q]));
            asm("fma.rn.f32x2 %0, %1, %2, %0;" : "+l"(acc2) : "l"(h2[q]), "l"(w2[2][q]));
            asm("fma.rn.f32x2 %0, %1, %2, %0;" : "+l"(acc3) : "l"(h2[q]), "l"(w2[3][q]));
        }
        float a0, a1, a2, a3, hq;
        unpackf2(acc0, a0, hq); a0 += hq;
        unpackf2(acc1, a1, hq); a1 += hq;
        unpackf2(acc2, a2, hq); a2 += hq;
        unpackf2(acc3, a3, hq); a3 += hq;
#pragma unroll
        for (int off = 1; off < 16; off <<= 1) {
            a0 += __shfl_xor_sync(0xffffffffu, a0, off);
            a1 += __shfl_xor_sync(0xffffffffu, a1, off);
            a2 += __shfl_xor_sync(0xffffffffu, a2, off);
            a3 += __shfl_xor_sync(0xffffffffu, a3, off);
        }

        float4 yv;
        yv.x = fast_tanh(wv.x + ub.x + a0);
        yv.y = fast_tanh(wv.y + ub.y + a1);
        yv.z = fast_tanh(wv.z + ub.z + a2);
        yv.w = fast_tanh(wv.w + ub.w + a3);

        if ((lane & 15) == 8) *(float4*)(out_b + (size_t)t * HD + j0) = yv;

        if (t < T_LEN - 1 && prod) {
            const int wbuf = t & 1;
            unsigned long long y01 = packf2(yv.x, yv.y);
            unsigned long long y23 = packf2(yv.z, yv.w);
            unsigned a = dsth + (unsigned)(wbuf * 2048) + stoff;
            asm volatile("st.shared::cluster.b64 [%0], %1;" :: "r"(a),     "l"(y01) : "memory");
            asm volatile("st.shared::cluster.b64 [%0], %1;" :: "r"(a + 8), "l"(y23) : "memory");
            asm volatile("mbarrier.arrive.release.cluster.shared::cluster.b64 _, [%0];"
                         :: "r"(dstm + (unsigned)(wbuf * 8)) : "memory");
        }
    }

    asm volatile("barrier.cluster.arrive.aligned;" ::: "memory");
    asm volatile("barrier.cluster.wait.aligned;"   ::: "memory");
}

// ---------------------------------------------------------------------------
extern "C" void kernel_launch(void* const* d_in, const int* in_sizes, int n_in,
                              void* d_out, int out_size)
{
    const float* x      = (const float*)d_in[0];
    const float* l0_wr  = (const float*)d_in[1];
    const float* l0_wi  = (const float*)d_in[2];
    const float* l0_wbr = (const float*)d_in[3];
    const float* l0_wbi = (const float*)d_in[4];
    const float* l0_ur  = (const float*)d_in[5];
    const float* l0_ui  = (const float*)d_in[6];
    const float* l0_ubr = (const float*)d_in[7];
    const float* l0_ubi = (const float*)d_in[8];
    const float* l1_wr  = (const float*)d_in[9];
    const float* l1_wi  = (const float*)d_in[10];
    const float* l1_wbr = (const float*)d_in[11];
    const float* l1_wbi = (const float*)d_in[12];
    const float* l1_ur  = (const float*)d_in[13];
    const float* l1_ui  = (const float*)d_in[14];
    const float* l1_ubr = (const float*)d_in[15];
    const float* l1_ubi = (const float*)d_in[16];

    float* out = (float*)d_out;

    void *p_wx_v = nullptr, *p_h0_v = nullptr;
    cudaGetSymbolAddress(&p_wx_v, g_wx);
    cudaGetSymbolAddress(&p_h0_v, g_h0);
    float* p_wx = (float*)p_wx_v;
    float* p_h0 = (float*)p_h0_v;

    dim3 pgrid(NROWS / 128, HD / 128);

    proj_kernel<<<pgrid, 256>>>(x, l0_wr, l0_wi, l0_wbr, l0_wbi, p_wx);
    scan_kernel<<<64, 256>>>(p_wx, l0_ur, l0_ui, l0_ubr, l0_ubi, p_h0);
    proj_kernel<<<pgrid, 256>>>(p_h0, l1_wr, l1_wi, l1_wbr, l1_wbi, p_wx);
    scan_kernel<<<64, 256>>>(p_wx, l1_ur, l1_ui, l1_ubr, l1_ubi, out);
}

// round 3
// speedup vs baseline: 2.0621x; 1.4524x over previous
#include <cuda_runtime.h>
#include <cstddef>

#define BATCH   8
#define T_LEN   4096
#define HC      256
#define HD      512
#define NROWS   (BATCH * T_LEN)

__device__ float g_wx[NROWS * HD];   // input-projection output
__device__ float g_h0[NROWS * HD];   // layer-0 hidden states

// ---------------------------------------------------------------- helpers
static __device__ __forceinline__ unsigned su32(const void* p) {
    return (unsigned)__cvta_generic_to_shared(p);
}
static __device__ __forceinline__ unsigned long long packf2(float lo, float hi) {
    unsigned long long r;
    asm("mov.b64 %0, {%1, %2};" : "=l"(r) : "f"(lo), "f"(hi));
    return r;
}
static __device__ __forceinline__ void unpackf2(unsigned long long v, float& lo, float& hi) {
    asm("mov.b64 {%0, %1}, %2;" : "=f"(lo), "=f"(hi) : "l"(v));
}
static __device__ __forceinline__ float fast_tanh(float x) {
    float e = __expf(2.0f * x);
    return 1.0f - __fdividef(2.0f, e + 1.0f);
}
static __device__ __forceinline__ void mbar_wait(unsigned addr, unsigned parity) {
    asm volatile(
        "{\n\t.reg .pred P;\n"
        "LW_%=:\n\t"
        "mbarrier.try_wait.parity.acquire.cluster.shared::cta.b64 P, [%0], %1, 0x989680;\n\t"
        "@P bra LD_%=;\n\t"
        "bra LW_%=;\n"
        "LD_%=:\n\t}"
        :: "r"(addr), "r"(parity) : "memory");
}

// ---------------------------------------------------------------------------
// Projection GEMM (unchanged): Y[N,512] = X[N,512] @ Mw[512,512] + bias
// ---------------------------------------------------------------------------
__global__ __launch_bounds__(256) void proj_kernel(
    const float* __restrict__ X,
    const float* __restrict__ wr, const float* __restrict__ wi,
    const float* __restrict__ br, const float* __restrict__ bi,
    float* __restrict__ Y)
{
    __shared__ float As[16][132];
    __shared__ float Bs[16][132];

    const int bm  = blockIdx.x * 128;
    const int bn  = blockIdx.y * 128;
    const int tid = threadIdx.x;
    const int tx  = tid & 15;
    const int ty  = tid >> 4;

    const int am = tid >> 1;
    const int ak = (tid & 1) * 8;
    const int bk = tid >> 4;
    const int bj = (tid & 15) * 8;
    const bool jhi = (bn + bj) >= 256;
    const int  jj  = (bn + bj) & 255;

    float acc[8][8];
#pragma unroll
    for (int r = 0; r < 8; ++r)
#pragma unroll
        for (int c = 0; c < 8; ++c) acc[r][c] = 0.f;

    for (int k0 = 0; k0 < HD; k0 += 16) {
        const float* xrow = X + (size_t)(bm + am) * HD + k0 + ak;
        float4 a0 = *(const float4*)(xrow);
        float4 a1 = *(const float4*)(xrow + 4);
        As[ak + 0][am] = a0.x; As[ak + 1][am] = a0.y;
        As[ak + 2][am] = a0.z; As[ak + 3][am] = a0.w;
        As[ak + 4][am] = a1.x; As[ak + 5][am] = a1.y;
        As[ak + 6][am] = a1.z; As[ak + 7][am] = a1.w;
        {
            int k = k0 + bk;
            float4 b0, b1;
            if (k < 256) {
                const float* src = (jhi ? wi : wr) + (size_t)k * 256 + jj;
                b0 = *(const float4*)(src);
                b1 = *(const float4*)(src + 4);
            } else {
                const float* src = (jhi ? wr : wi) + (size_t)(k - 256) * 256 + jj;
                b0 = *(const float4*)(src);
                b1 = *(const float4*)(src + 4);
                if (!jhi) {
                    b0.x = -b0.x; b0.y = -b0.y; b0.z = -b0.z; b0.w = -b0.w;
                    b1.x = -b1.x; b1.y = -b1.y; b1.z = -b1.z; b1.w = -b1.w;
                }
            }
            *(float4*)&Bs[bk][bj]     = b0;
            *(float4*)&Bs[bk][bj + 4] = b1;
        }
        __syncthreads();

#pragma unroll
        for (int kk = 0; kk < 16; ++kk) {
            float4 av0 = *(const float4*)&As[kk][ty * 8];
            float4 av1 = *(const float4*)&As[kk][ty * 8 + 4];
            float4 bv0 = *(const float4*)&Bs[kk][tx * 8];
            float4 bv1 = *(const float4*)&Bs[kk][tx * 8 + 4];
            float a[8] = {av0.x, av0.y, av0.z, av0.w, av1.x, av1.y, av1.z, av1.w};
            float b[8] = {bv0.x, bv0.y, bv0.z, bv0.w, bv1.x, bv1.y, bv1.z, bv1.w};
#pragma unroll
            for (int r = 0; r < 8; ++r)
#pragma unroll
                for (int c = 0; c < 8; ++c)
                    acc[r][c] = fmaf(a[r], b[c], acc[r][c]);
        }
        __syncthreads();
    }

    const int col0 = bn + tx * 8;
    float bias[8];
#pragma unroll
    for (int c = 0; c < 8; ++c) {
        int j = col0 + c;
        bias[c] = (j < 256) ? br[j] : bi[j - 256];
    }
#pragma unroll
    for (int r = 0; r < 8; ++r) {
        float* yrow = Y + (size_t)(bm + ty * 8 + r) * HD + col0;
        float4 v0 = make_float4(acc[r][0] + bias[0], acc[r][1] + bias[1],
                                acc[r][2] + bias[2], acc[r][3] + bias[3]);
        float4 v1 = make_float4(acc[r][4] + bias[4], acc[r][5] + bias[5],
                                acc[r][6] + bias[6], acc[r][7] + bias[7]);
        *(float4*)(yrow)     = v0;
        *(float4*)(yrow + 4) = v1;
    }
}

// ---------------------------------------------------------------------------
// Recurrent scan: 8 clusters x 8 CTAs x 256 threads.
// h exchange: st.async (DSMEM + HW tx accounting) into double-buffered smem.
// Barrier per buffer: init count = 8 (one arrive.expect_tx(256B) per warp at
// re-arm). Producers issue NO arrives — complete_tx rides with each st.async.
// Re-arm race-free: warp re-arms buffer b right after waiting on b; remote
// writes to b's next phase are gated on this warp's later stores (in-order
// issue + __syncwarp).
// ---------------------------------------------------------------------------
__global__ void __cluster_dims__(8, 1, 1) __launch_bounds__(256, 1)
scan_kernel(const float* __restrict__ wx,
            const float* __restrict__ ur, const float* __restrict__ ui,
            const float* __restrict__ ubr, const float* __restrict__ ubi,
            float* __restrict__ out)
{
    __shared__ float hbuf[2][HD];
    __shared__ __align__(8) unsigned long long mbar[2];

    unsigned rank;
    asm("mov.u32 %0, %%cluster_ctarank;" : "=r"(rank));
    const int b    = blockIdx.x >> 3;
    const int tid  = threadIdx.x;
    const int lane = tid & 31;
    const int jg   = tid >> 4;
    const int kg   = tid & 15;
    const int j0   = (int)rank * 64 + jg * 4;
    const int jj   = j0 & 255;
    const bool jhi = j0 >= 256;

    const unsigned hb_u32 = su32(&hbuf[0][0]);
    const unsigned mb_u32 = su32(&mbar[0]);

    if (tid == 0) {
        asm volatile("mbarrier.init.shared.b64 [%0], %1;" :: "r"(mb_u32),     "r"(8u) : "memory");
        asm volatile("mbarrier.init.shared.b64 [%0], %1;" :: "r"(mb_u32 + 8), "r"(8u) : "memory");
    }
    __syncthreads();
    // arm phase 0 of both buffers: 8 warps x expect 256B = 2048B each
    if (lane == 0) {
        asm volatile("mbarrier.arrive.expect_tx.shared::cta.b64 _, [%0], %1;"
                     :: "r"(mb_u32),     "r"(256u) : "memory");
        asm volatile("mbarrier.arrive.expect_tx.shared::cta.b64 _, [%0], %1;"
                     :: "r"(mb_u32 + 8), "r"(256u) : "memory");
    }
    __syncthreads();
    asm volatile("barrier.cluster.arrive.aligned;" ::: "memory");
    asm volatile("barrier.cluster.wait.aligned;"   ::: "memory");

    // ---- weight slice into registers, packed f32x2 along k ----
    unsigned long long w2[4][16];
#pragma unroll
    for (int q = 0; q < 8; ++q) {
        const int k = q * 64 + kg * 4;
        float4 r0, r1, r2, r3;
        if (k < 256) {
            const float* src = (jhi ? ui : ur) + (size_t)k * 256 + jj;
            r0 = *(const float4*)(src);
            r1 = *(const float4*)(src + 256);
            r2 = *(const float4*)(src + 512);
            r3 = *(const float4*)(src + 768);
        } else {
            const float* src = (jhi ? ur : ui) + (size_t)(k - 256) * 256 + jj;
            const float s = jhi ? 1.f : -1.f;
            r0 = *(const float4*)(src);
            r1 = *(const float4*)(src + 256);
            r2 = *(const float4*)(src + 512);
            r3 = *(const float4*)(src + 768);
            r0.x *= s; r0.y *= s; r0.z *= s; r0.w *= s;
            r1.x *= s; r1.y *= s; r1.z *= s; r1.w *= s;
            r2.x *= s; r2.y *= s; r2.z *= s; r2.w *= s;
            r3.x *= s; r3.y *= s; r3.z *= s; r3.w *= s;
        }
        w2[0][2*q]   = packf2(r0.x, r1.x);
        w2[1][2*q]   = packf2(r0.y, r1.y);
        w2[2][2*q]   = packf2(r0.z, r1.z);
        w2[3][2*q]   = packf2(r0.w, r1.w);
        w2[0][2*q+1] = packf2(r2.x, r3.x);
        w2[1][2*q+1] = packf2(r2.y, r3.y);
        w2[2][2*q+1] = packf2(r2.z, r3.z);
        w2[3][2*q+1] = packf2(r2.w, r3.w);
    }
    const float4 ub = jhi ? *(const float4*)(ubi + jj)
                          : *(const float4*)(ubr + jj);

    // producers: lanes 0-7 and 16-23; each stores its 16B j-slice to dst=lane&7
    const bool prod = ((lane >> 3) & 1) == 0;
    const int  dst  = lane & 7;
    unsigned dsth, dstm;
    asm("mapa.shared::cluster.u32 %0, %1, %2;" : "=r"(dsth) : "r"(hb_u32), "r"(dst));
    asm("mapa.shared::cluster.u32 %0, %1, %2;" : "=r"(dstm) : "r"(mb_u32), "r"(dst));
    const unsigned stoff = (unsigned)(rank * 256 + jg * 16);

    const float* wx_b  = wx  + (size_t)b * (T_LEN * HD);
    float*       out_b = out + (size_t)b * (T_LEN * HD);

    // ---- t = 0 (h_prev = 0) ----
    {
        float4 wv = *(const float4*)(wx_b + j0);
        float4 yv;
        yv.x = fast_tanh(wv.x + ub.x);
        yv.y = fast_tanh(wv.y + ub.y);
        yv.z = fast_tanh(wv.z + ub.z);
        yv.w = fast_tanh(wv.w + ub.w);
        if (prod) {
            unsigned long long y01 = packf2(yv.x, yv.y);
            unsigned long long y23 = packf2(yv.z, yv.w);
            unsigned a = dsth + stoff;   // buf 0
            asm volatile("st.async.shared::cluster.mbarrier::complete_tx::bytes.b64 [%0], %1, [%2];"
                         :: "r"(a),     "l"(y01), "r"(dstm) : "memory");
            asm volatile("st.async.shared::cluster.mbarrier::complete_tx::bytes.b64 [%0], %1, [%2];"
                         :: "r"(a + 8), "l"(y23), "r"(dstm) : "memory");
        }
        if ((lane & 15) == 8) *(float4*)(out_b + j0) = yv;
    }

    for (int t = 1; t < T_LEN; ++t) {
        float4 wv = *(const float4*)(wx_b + (size_t)t * HD + j0);

        const int use  = t - 1;
        const int rbuf = use & 1;
        mbar_wait(mb_u32 + rbuf * 8, (unsigned)((use >> 1) & 1));

        // issue h loads first (latency covers re-arm)
        unsigned long long h2[16];
        const float* hp = &hbuf[rbuf][0];
#pragma unroll
        for (int q = 0; q < 8; ++q) {
            ulonglong2 v = *(const ulonglong2*)(hp + q * 64 + kg * 4);
            h2[2*q]   = v.x;
            h2[2*q+1] = v.y;
        }

        // re-arm this buffer's next phase (8 arrivals x 256B); must precede
        // this warp's st.async below (in-order issue + syncwarp).
        if (lane == 0) {
            asm volatile("mbarrier.arrive.expect_tx.shared::cta.b64 _, [%0], %1;"
                         :: "r"(mb_u32 + rbuf * 8), "r"(256u) : "memory");
        }
        __syncwarp();

        unsigned long long acc0 = 0, acc1 = 0, acc2 = 0, acc3 = 0;
#pragma unroll
        for (int q = 0; q < 16; ++q) {
            asm("fma.rn.f32x2 %0, %1, %2, %0;" : "+l"(acc0) : "l"(h2[q]), "l"(w2[0][q]));
            asm("fma.rn.f32x2 %0, %1, %2, %0;" : "+l"(acc1) : "l"(h2[q]), "l"(w2[1][q]));
            asm("fma.rn.f32x2 %0, %1, %2, %0;" : "+l"(acc2) : "l"(h2[q]), "l"(w2[2][q]));
            asm("fma.rn.f32x2 %0, %1, %2, %0;" : "+l"(acc3) : "l"(h2[q]), "l"(w2[3][q]));
        }
        float a0, a1, a2, a3, hq;
        unpackf2(acc0, a0, hq); a0 += hq;
        unpackf2(acc1, a1, hq); a1 += hq;
        unpackf2(acc2, a2, hq); a2 += hq;
        unpackf2(acc3, a3, hq); a3 += hq;
#pragma unroll
        for (int off = 1; off < 16; off <<= 1) {
            a0 += __shfl_xor_sync(0xffffffffu, a0, off);
            a1 += __shfl_xor_sync(0xffffffffu, a1, off);
            a2 += __shfl_xor_sync(0xffffffffu, a2, off);
            a3 += __shfl_xor_sync(0xffffffffu, a3, off);
        }

        float4 yv;
        yv.x = fast_tanh(wv.x + ub.x + a0);
        yv.y = fast_tanh(wv.y + ub.y + a1);
        yv.z = fast_tanh(wv.z + ub.z + a2);
        yv.w = fast_tanh(wv.w + ub.w + a3);

        // broadcast first (critical path), then global store
        if (t < T_LEN - 1 && prod) {
            const int wbuf = t & 1;
            unsigned long long y01 = packf2(yv.x, yv.y);
            unsigned long long y23 = packf2(yv.z, yv.w);
            unsigned a  = dsth + (unsigned)(wbuf * 2048) + stoff;
            unsigned mb = dstm + (unsigned)(wbuf * 8);
            asm volatile("st.async.shared::cluster.mbarrier::complete_tx::bytes.b64 [%0], %1, [%2];"
                         :: "r"(a),     "l"(y01), "r"(mb) : "memory");
            asm volatile("st.async.shared::cluster.mbarrier::complete_tx::bytes.b64 [%0], %1, [%2];"
                         :: "r"(a + 8), "l"(y23), "r"(mb) : "memory");
        }
        if ((lane & 15) == 8) *(float4*)(out_b + (size_t)t * HD + j0) = yv;
    }

    asm volatile("barrier.cluster.arrive.aligned;" ::: "memory");
    asm volatile("barrier.cluster.wait.aligned;"   ::: "memory");
}

// ---------------------------------------------------------------------------
extern "C" void kernel_launch(void* const* d_in, const int* in_sizes, int n_in,
                              void* d_out, int out_size)
{
    const float* x      = (const float*)d_in[0];
    const float* l0_wr  = (const float*)d_in[1];
    const float* l0_wi  = (const float*)d_in[2];
    const float* l0_wbr = (const float*)d_in[3];
    const float* l0_wbi = (const float*)d_in[4];
    const float* l0_ur  = (const float*)d_in[5];
    const float* l0_ui  = (const float*)d_in[6];
    const float* l0_ubr = (const float*)d_in[7];
    const float* l0_ubi = (const float*)d_in[8];
    const float* l1_wr  = (const float*)d_in[9];
    const float* l1_wi  = (const float*)d_in[10];
    const float* l1_wbr = (const float*)d_in[11];
    const float* l1_wbi = (const float*)d_in[12];
    const float* l1_ur  = (const float*)d_in[13];
    const float* l1_ui  = (const float*)d_in[14];
    const float* l1_ubr = (const float*)d_in[15];
    const float* l1_ubi = (const float*)d_in[16];

    float* out = (float*)d_out;

    void *p_wx_v = nullptr, *p_h0_v = nullptr;
    cudaGetSymbolAddress(&p_wx_v, g_wx);
    cudaGetSymbolAddress(&p_h0_v, g_h0);
    float* p_wx = (float*)p_wx_v;
    float* p_h0 = (float*)p_h0_v;

    dim3 pgrid(NROWS / 128, HD / 128);

    proj_kernel<<<pgrid, 256>>>(x, l0_wr, l0_wi, l0_wbr, l0_wbi, p_wx);
    scan_kernel<<<64, 256>>>(p_wx, l0_ur, l0_ui, l0_ubr, l0_ubi, p_h0);
    proj_kernel<<<pgrid, 256>>>(p_h0, l1_wr, l1_wi, l1_wbr, l1_wbi, p_wx);
    scan_kernel<<<64, 256>>>(p_wx, l1_ur, l1_ui, l1_ubr, l1_ubi, out);
}

// round 4
// speedup vs baseline: 2.1463x; 1.0408x over previous
#include <cuda_runtime.h>
#include <cstddef>

#define BATCH   8
#define T_LEN   4096
#define HC      256
#define HD      512
#define NROWS   (BATCH * T_LEN)

__device__ float g_wx[NROWS * HD];   // input-projection output
__device__ float g_h0[NROWS * HD];   // layer-0 hidden states

// ---------------------------------------------------------------- helpers
static __device__ __forceinline__ unsigned su32(const void* p) {
    return (unsigned)__cvta_generic_to_shared(p);
}
static __device__ __forceinline__ unsigned long long packf2(float lo, float hi) {
    unsigned long long r;
    asm("mov.b64 %0, {%1, %2};" : "=l"(r) : "f"(lo), "f"(hi));
    return r;
}
static __device__ __forceinline__ void unpackf2(unsigned long long v, float& lo, float& hi) {
    asm("mov.b64 {%0, %1}, %2;" : "=f"(lo), "=f"(hi) : "l"(v));
}
static __device__ __forceinline__ float fast_tanh(float x) {
    float e = __expf(2.0f * x);
    return 1.0f - __fdividef(2.0f, e + 1.0f);
}
static __device__ __forceinline__ void mbar_wait(unsigned addr, unsigned parity) {
    asm volatile(
        "{\n\t.reg .pred P;\n"
        "LW_%=:\n\t"
        "mbarrier.try_wait.parity.acquire.cluster.shared::cta.b64 P, [%0], %1, 0x989680;\n\t"
        "@P bra LD_%=;\n\t"
        "bra LW_%=;\n"
        "LD_%=:\n\t}"
        :: "r"(addr), "r"(parity) : "memory");
}

// ---------------------------------------------------------------------------
// Projection GEMM (unchanged): Y[N,512] = X[N,512] @ Mw[512,512] + bias
// ---------------------------------------------------------------------------
__global__ __launch_bounds__(256) void proj_kernel(
    const float* __restrict__ X,
    const float* __restrict__ wr, const float* __restrict__ wi,
    const float* __restrict__ br, const float* __restrict__ bi,
    float* __restrict__ Y)
{
    __shared__ float As[16][132];
    __shared__ float Bs[16][132];

    const int bm  = blockIdx.x * 128;
    const int bn  = blockIdx.y * 128;
    const int tid = threadIdx.x;
    const int tx  = tid & 15;
    const int ty  = tid >> 4;

    const int am = tid >> 1;
    const int ak = (tid & 1) * 8;
    const int bk = tid >> 4;
    const int bj = (tid & 15) * 8;
    const bool jhi = (bn + bj) >= 256;
    const int  jj  = (bn + bj) & 255;

    float acc[8][8];
#pragma unroll
    for (int r = 0; r < 8; ++r)
#pragma unroll
        for (int c = 0; c < 8; ++c) acc[r][c] = 0.f;

    for (int k0 = 0; k0 < HD; k0 += 16) {
        const float* xrow = X + (size_t)(bm + am) * HD + k0 + ak;
        float4 a0 = *(const float4*)(xrow);
        float4 a1 = *(const float4*)(xrow + 4);
        As[ak + 0][am] = a0.x; As[ak + 1][am] = a0.y;
        As[ak + 2][am] = a0.z; As[ak + 3][am] = a0.w;
        As[ak + 4][am] = a1.x; As[ak + 5][am] = a1.y;
        As[ak + 6][am] = a1.z; As[ak + 7][am] = a1.w;
        {
            int k = k0 + bk;
            float4 b0, b1;
            if (k < 256) {
                const float* src = (jhi ? wi : wr) + (size_t)k * 256 + jj;
                b0 = *(const float4*)(src);
                b1 = *(const float4*)(src + 4);
            } else {
                const float* src = (jhi ? wr : wi) + (size_t)(k - 256) * 256 + jj;
                b0 = *(const float4*)(src);
                b1 = *(const float4*)(src + 4);
                if (!jhi) {
                    b0.x = -b0.x; b0.y = -b0.y; b0.z = -b0.z; b0.w = -b0.w;
                    b1.x = -b1.x; b1.y = -b1.y; b1.z = -b1.z; b1.w = -b1.w;
                }
            }
            *(float4*)&Bs[bk][bj]     = b0;
            *(float4*)&Bs[bk][bj + 4] = b1;
        }
        __syncthreads();

#pragma unroll
        for (int kk = 0; kk < 16; ++kk) {
            float4 av0 = *(const float4*)&As[kk][ty * 8];
            float4 av1 = *(const float4*)&As[kk][ty * 8 + 4];
            float4 bv0 = *(const float4*)&Bs[kk][tx * 8];
            float4 bv1 = *(const float4*)&Bs[kk][tx * 8 + 4];
            float a[8] = {av0.x, av0.y, av0.z, av0.w, av1.x, av1.y, av1.z, av1.w};
            float b[8] = {bv0.x, bv0.y, bv0.z, bv0.w, bv1.x, bv1.y, bv1.z, bv1.w};
#pragma unroll
            for (int r = 0; r < 8; ++r)
#pragma unroll
                for (int c = 0; c < 8; ++c)
                    acc[r][c] = fmaf(a[r], b[c], acc[r][c]);
        }
        __syncthreads();
    }

    const int col0 = bn + tx * 8;
    float bias[8];
#pragma unroll
    for (int c = 0; c < 8; ++c) {
        int j = col0 + c;
        bias[c] = (j < 256) ? br[j] : bi[j - 256];
    }
#pragma unroll
    for (int r = 0; r < 8; ++r) {
        float* yrow = Y + (size_t)(bm + ty * 8 + r) * HD + col0;
        float4 v0 = make_float4(acc[r][0] + bias[0], acc[r][1] + bias[1],
                                acc[r][2] + bias[2], acc[r][3] + bias[3]);
        float4 v1 = make_float4(acc[r][4] + bias[4], acc[r][5] + bias[5],
                                acc[r][6] + bias[6], acc[r][7] + bias[7]);
        *(float4*)(yrow)     = v0;
        *(float4*)(yrow + 4) = v1;
    }
}

// ---------------------------------------------------------------------------
// Recurrent scan: 8 clusters x 8 CTAs x 256 threads.
// Per step each CTA: computes its 64-output slice, stages it (256 B) in local
// smem, then ONE thread issues 8x cp.async.bulk (256 B) to all peers' h
// buffers with mbarrier complete_tx. Each dst barrier sees 8 tx events/step
// (vs 256 scalar st.async events before). Barriers: count=1, re-armed each
// phase by tid0 with arrive.expect_tx(2048).
// ---------------------------------------------------------------------------
__global__ void __cluster_dims__(8, 1, 1) __launch_bounds__(256, 1)
scan_kernel(const float* __restrict__ wx,
            const float* __restrict__ ur, const float* __restrict__ ui,
            const float* __restrict__ ubr, const float* __restrict__ ubi,
            float* __restrict__ out)
{
    __shared__ float hbuf[2][HD];                       // 2 x 2048 B
    __shared__ __align__(16) float stage[64];           // this CTA's slice
    __shared__ __align__(8) unsigned long long mbar[2];

    unsigned rank;
    asm("mov.u32 %0, %%cluster_ctarank;" : "=r"(rank));
    const int b    = blockIdx.x >> 3;
    const int tid  = threadIdx.x;
    const int lane = tid & 31;
    const int jg   = tid >> 4;
    const int kg   = tid & 15;
    const int j0   = (int)rank * 64 + jg * 4;
    const int jj   = j0 & 255;
    const bool jhi = j0 >= 256;

    const unsigned hb_u32 = su32(&hbuf[0][0]);
    const unsigned st_u32 = su32(&stage[0]);
    const unsigned mb_u32 = su32(&mbar[0]);

    if (tid == 0) {
        asm volatile("mbarrier.init.shared.b64 [%0], %1;" :: "r"(mb_u32),     "r"(1u) : "memory");
        asm volatile("mbarrier.init.shared.b64 [%0], %1;" :: "r"(mb_u32 + 8), "r"(1u) : "memory");
        // arm phase 0 of both buffers: expect 8 x 256 B
        asm volatile("mbarrier.arrive.expect_tx.shared::cta.b64 _, [%0], %1;"
                     :: "r"(mb_u32),     "r"(2048u) : "memory");
        asm volatile("mbarrier.arrive.expect_tx.shared::cta.b64 _, [%0], %1;"
                     :: "r"(mb_u32 + 8), "r"(2048u) : "memory");
    }
    __syncthreads();
    asm volatile("barrier.cluster.arrive.aligned;" ::: "memory");
    asm volatile("barrier.cluster.wait.aligned;"   ::: "memory");

    // destination addresses for the 8 peers (used by tid0 only)
    unsigned dsth[8], dstm[8];
#pragma unroll
    for (int d = 0; d < 8; ++d) {
        asm("mapa.shared::cluster.u32 %0, %1, %2;" : "=r"(dsth[d]) : "r"(hb_u32), "r"(d));
        asm("mapa.shared::cluster.u32 %0, %1, %2;" : "=r"(dstm[d]) : "r"(mb_u32), "r"(d));
    }
    const unsigned my_off = (unsigned)(rank * 256);   // byte offset of my slice

    // ---- weight slice into registers, packed f32x2 along k ----
    unsigned long long w2[4][16];
#pragma unroll
    for (int q = 0; q < 8; ++q) {
        const int k = q * 64 + kg * 4;
        float4 r0, r1, r2, r3;
        if (k < 256) {
            const float* src = (jhi ? ui : ur) + (size_t)k * 256 + jj;
            r0 = *(const float4*)(src);
            r1 = *(const float4*)(src + 256);
            r2 = *(const float4*)(src + 512);
            r3 = *(const float4*)(src + 768);
        } else {
            const float* src = (jhi ? ur : ui) + (size_t)(k - 256) * 256 + jj;
            const float s = jhi ? 1.f : -1.f;
            r0 = *(const float4*)(src);
            r1 = *(const float4*)(src + 256);
            r2 = *(const float4*)(src + 512);
            r3 = *(const float4*)(src + 768);
            r0.x *= s; r0.y *= s; r0.z *= s; r0.w *= s;
            r1.x *= s; r1.y *= s; r1.z *= s; r1.w *= s;
            r2.x *= s; r2.y *= s; r2.z *= s; r2.w *= s;
            r3.x *= s; r3.y *= s; r3.z *= s; r3.w *= s;
        }
        w2[0][2*q]   = packf2(r0.x, r1.x);
        w2[1][2*q]   = packf2(r0.y, r1.y);
        w2[2][2*q]   = packf2(r0.z, r1.z);
        w2[3][2*q]   = packf2(r0.w, r1.w);
        w2[0][2*q+1] = packf2(r2.x, r3.x);
        w2[1][2*q+1] = packf2(r2.y, r3.y);
        w2[2][2*q+1] = packf2(r2.z, r3.z);
        w2[3][2*q+1] = packf2(r2.w, r3.w);
    }
    const float4 ub = jhi ? *(const float4*)(ubi + jj)
                          : *(const float4*)(ubr + jj);

    const float* wx_b  = wx  + (size_t)b * (T_LEN * HD);
    float*       out_b = out + (size_t)b * (T_LEN * HD);

    // ---- t = 0 (h_prev = 0) ----
    {
        float4 wv = *(const float4*)(wx_b + j0);
        float4 yv;
        yv.x = fast_tanh(wv.x + ub.x);
        yv.y = fast_tanh(wv.y + ub.y);
        yv.z = fast_tanh(wv.z + ub.z);
        yv.w = fast_tanh(wv.w + ub.w);
        if ((lane & 15) == 0) *(float4*)&stage[jg * 4] = yv;
        if ((lane & 15) == 8) *(float4*)(out_b + j0) = yv;
        __syncthreads();
        if (tid == 0) {
            asm volatile("fence.proxy.async.shared::cta;" ::: "memory");
#pragma unroll
            for (int d = 0; d < 8; ++d) {
                asm volatile(
                    "cp.async.bulk.shared::cluster.shared::cta.mbarrier::complete_tx::bytes "
                    "[%0], [%1], %2, [%3];"
                    :: "r"(dsth[d] + my_off), "r"(st_u32), "r"(256u), "r"(dstm[d])
                    : "memory");
            }
        }
    }

    for (int t = 1; t < T_LEN; ++t) {
        float4 wv = *(const float4*)(wx_b + (size_t)t * HD + j0);

        const int use  = t - 1;
        const int rbuf = use & 1;
        mbar_wait(mb_u32 + rbuf * 8, (unsigned)((use >> 1) & 1));

        // re-arm this buffer for its next phase (before this CTA's bulk below)
        if (tid == 0) {
            asm volatile("mbarrier.arrive.expect_tx.shared::cta.b64 _, [%0], %1;"
                         :: "r"(mb_u32 + rbuf * 8), "r"(2048u) : "memory");
        }

        unsigned long long h2[16];
        const float* hp = &hbuf[rbuf][0];
#pragma unroll
        for (int q = 0; q < 8; ++q) {
            ulonglong2 v = *(const ulonglong2*)(hp + q * 64 + kg * 4);
            h2[2*q]   = v.x;
            h2[2*q+1] = v.y;
        }

        unsigned long long acc0 = 0, acc1 = 0, acc2 = 0, acc3 = 0;
#pragma unroll
        for (int q = 0; q < 16; ++q) {
            asm("fma.rn.f32x2 %0, %1, %2, %0;" : "+l"(acc0) : "l"(h2[q]), "l"(w2[0][q]));
            asm("fma.rn.f32x2 %0, %1, %2, %0;" : "+l"(acc1) : "l"(h2[q]), "l"(w2[1][q]));
            asm("fma.rn.f32x2 %0, %1, %2, %0;" : "+l"(acc2) : "l"(h2[q]), "l"(w2[2][q]));
            asm("fma.rn.f32x2 %0, %1, %2, %0;" : "+l"(acc3) : "l"(h2[q]), "l"(w2[3][q]));
        }
        float a0, a1, a2, a3, hq;
        unpackf2(acc0, a0, hq); a0 += hq;
        unpackf2(acc1, a1, hq); a1 += hq;
        unpackf2(acc2, a2, hq); a2 += hq;
        unpackf2(acc3, a3, hq); a3 += hq;
#pragma unroll
        for (int off = 1; off < 16; off <<= 1) {
            a0 += __shfl_xor_sync(0xffffffffu, a0, off);
            a1 += __shfl_xor_sync(0xffffffffu, a1, off);
            a2 += __shfl_xor_sync(0xffffffffu, a2, off);
            a3 += __shfl_xor_sync(0xffffffffu, a3, off);
        }

        float4 yv;
        yv.x = fast_tanh(wv.x + ub.x + a0);
        yv.y = fast_tanh(wv.y + ub.y + a1);
        yv.z = fast_tanh(wv.z + ub.z + a2);
        yv.w = fast_tanh(wv.w + ub.w + a3);

        if ((lane & 15) == 0) *(float4*)&stage[jg * 4] = yv;
        if ((lane & 15) == 8) *(float4*)(out_b + (size_t)t * HD + j0) = yv;

        if (t < T_LEN - 1) {
            __syncthreads();
            if (tid == 0) {
                const unsigned boff = (unsigned)((t & 1) * 2048) + my_off;
                const unsigned moff = (unsigned)((t & 1) * 8);
                asm volatile("fence.proxy.async.shared::cta;" ::: "memory");
#pragma unroll
                for (int d = 0; d < 8; ++d) {
                    asm volatile(
                        "cp.async.bulk.shared::cluster.shared::cta.mbarrier::complete_tx::bytes "
                        "[%0], [%1], %2, [%3];"
                        :: "r"(dsth[d] + boff), "r"(st_u32), "r"(256u), "r"(dstm[d] + moff)
                        : "memory");
                }
            }
        }
    }

    asm volatile("barrier.cluster.arrive.aligned;" ::: "memory");
    asm volatile("barrier.cluster.wait.aligned;"   ::: "memory");
}

// ---------------------------------------------------------------------------
extern "C" void kernel_launch(void* const* d_in, const int* in_sizes, int n_in,
                              void* d_out, int out_size)
{
    const float* x      = (const float*)d_in[0];
    const float* l0_wr  = (const float*)d_in[1];
    const float* l0_wi  = (const float*)d_in[2];
    const float* l0_wbr = (const float*)d_in[3];
    const float* l0_wbi = (const float*)d_in[4];
    const float* l0_ur  = (const float*)d_in[5];
    const float* l0_ui  = (const float*)d_in[6];
    const float* l0_ubr = (const float*)d_in[7];
    const float* l0_ubi = (const float*)d_in[8];
    const float* l1_wr  = (const float*)d_in[9];
    const float* l1_wi  = (const float*)d_in[10];
    const float* l1_wbr = (const float*)d_in[11];
    const float* l1_wbi = (const float*)d_in[12];
    const float* l1_ur  = (const float*)d_in[13];
    const float* l1_ui  = (const float*)d_in[14];
    const float* l1_ubr = (const float*)d_in[15];
    const float* l1_ubi = (const float*)d_in[16];

    float* out = (float*)d_out;

    void *p_wx_v = nullptr, *p_h0_v = nullptr;
    cudaGetSymbolAddress(&p_wx_v, g_wx);
    cudaGetSymbolAddress(&p_h0_v, g_h0);
    float* p_wx = (float*)p_wx_v;
    float* p_h0 = (float*)p_h0_v;

    dim3 pgrid(NROWS / 128, HD / 128);

    proj_kernel<<<pgrid, 256>>>(x, l0_wr, l0_wi, l0_wbr, l0_wbi, p_wx);
    scan_kernel<<<64, 256>>>(p_wx, l0_ur, l0_ui, l0_ubr, l0_ubi, p_h0);
    proj_kernel<<<pgrid, 256>>>(p_h0, l1_wr, l1_wi, l1_wbr, l1_wbi, p_wx);
    scan_kernel<<<64, 256>>>(p_wx, l1_ur, l1_ui, l1_ubr, l1_ubi, out);
}